// round 2
// baseline (speedup 1.0000x reference)
#include <cuda_runtime.h>
#include <math.h>

// Problem constants
#define QS    512
#define BATCH 8
#define CDIM  1024
#define NHEAD 16
#define HCDIM 64
#define MMEM  1536
#define NTOK  (QS * BATCH)   // 4096

// Scratch (device globals: allocation-guard safe)
__device__ float g_q[NTOK * CDIM];
__device__ float g_k[NTOK * CDIM];
__device__ float g_v[NTOK * CDIM];
__device__ float g_x[NTOK * CDIM];

// ---------------------------------------------------------------------------
// GEMM: out[n][o] = sum_k A[n][k] * W[o][k] + bias[o]
// N = 4096, K = 1024, O = 1024. Block: 64 rows x 64 cols, 256 threads, 4x4
// microtile per thread, k-chunk 32.
// ---------------------------------------------------------------------------
__global__ __launch_bounds__(256) void gemm_nt_bias(
    const float* __restrict__ A, const float* __restrict__ W,
    const float* __restrict__ bias, float* __restrict__ out)
{
    __shared__ float As[32 * 64];  // transposed [k][n], stride 64 (float4 reads)
    __shared__ float Ws[32 * 65];  // transposed [k][o], stride 65 (scalar reads)

    const int tid = threadIdx.x;
    const int tx = tid & 15;       // covers 4 output cols
    const int ty = tid >> 4;       // covers 4 output rows
    const int n0 = blockIdx.y << 6;
    const int o0 = blockIdx.x << 6;
    const int lr = tid >> 3;       // loader row 0..31
    const int lk = (tid & 7) << 2; // loader k offset 0..28

    float acc[4][4] = {};

    for (int k0 = 0; k0 < CDIM; k0 += 32) {
        #pragma unroll
        for (int p = 0; p < 2; p++) {
            int r = lr + (p << 5);
            float4 av = *(const float4*)(A + (size_t)(n0 + r) * CDIM + k0 + lk);
            As[(lk + 0) * 64 + r] = av.x;
            As[(lk + 1) * 64 + r] = av.y;
            As[(lk + 2) * 64 + r] = av.z;
            As[(lk + 3) * 64 + r] = av.w;
            float4 wv = *(const float4*)(W + (size_t)(o0 + r) * CDIM + k0 + lk);
            Ws[(lk + 0) * 65 + r] = wv.x;
            Ws[(lk + 1) * 65 + r] = wv.y;
            Ws[(lk + 2) * 65 + r] = wv.z;
            Ws[(lk + 3) * 65 + r] = wv.w;
        }
        __syncthreads();

        #pragma unroll 16
        for (int kk = 0; kk < 32; kk++) {
            float4 a = *(const float4*)(As + kk * 64 + (ty << 2));
            float w0 = Ws[kk * 65 + (tx << 2) + 0];
            float w1 = Ws[kk * 65 + (tx << 2) + 1];
            float w2 = Ws[kk * 65 + (tx << 2) + 2];
            float w3 = Ws[kk * 65 + (tx << 2) + 3];
            acc[0][0] += a.x * w0; acc[0][1] += a.x * w1; acc[0][2] += a.x * w2; acc[0][3] += a.x * w3;
            acc[1][0] += a.y * w0; acc[1][1] += a.y * w1; acc[1][2] += a.y * w2; acc[1][3] += a.y * w3;
            acc[2][0] += a.z * w0; acc[2][1] += a.z * w1; acc[2][2] += a.z * w2; acc[2][3] += a.z * w3;
            acc[3][0] += a.w * w0; acc[3][1] += a.w * w1; acc[3][2] += a.w * w2; acc[3][3] += a.w * w3;
        }
        __syncthreads();
    }

    #pragma unroll
    for (int i = 0; i < 4; i++) {
        float* orow = out + (size_t)(n0 + (ty << 2) + i) * CDIM + o0 + (tx << 2);
        #pragma unroll
        for (int j = 0; j < 4; j++)
            orow[j] = acc[i][j] + bias[o0 + (tx << 2) + j];
    }
}

// ---------------------------------------------------------------------------
// Flash-attention over the combined (memory ++ new) KV sequence.
// Grid: (QS/64, BATCH*NHEAD). Block: 256 threads, 64q x 64k tiles.
// q/k/v live in [s][b][c] layout (GEMM output); memory_kv is (M,B,H,128).
// ---------------------------------------------------------------------------
__global__ __launch_bounds__(256) void attn_kernel(
    const float* __restrict__ qg, const float* __restrict__ kg,
    const float* __restrict__ vg, const float* __restrict__ memkv,
    const int* __restrict__ memlen, const int* __restrict__ padv,
    const unsigned char* __restrict__ mask, float* __restrict__ xout)
{
    extern __shared__ float sm[];
    float* Qs = sm;                 // [d][qi]  64x64, stride 64 (float4 reads)
    float* Ks = sm + 64 * 64;       // [d][kj]  64x65; reused as Ps[kj][qi]
    float* Vs = Ks + 64 * 65;       // [kj][c]  64x64, stride 64 (float4 reads)

    const int tid = threadIdx.x;
    const int tx = tid & 15;        // 4 key cols / 4 hc cols
    const int ty = tid >> 4;        // 4 query rows
    const int s0 = blockIdx.x << 6;
    const int b  = blockIdx.y >> 4;
    const int h  = blockIdx.y & 15;
    const int L  = memlen[b];
    const int P  = padv[b];
    const int Teff = L + P;

    // Load Q tile transposed, pre-scaled by temperature 1/sqrt(64)
    for (int c = tid; c < 1024; c += 256) {
        int qi = c >> 4;
        int dc = (c & 15) << 2;
        float4 qv = *(const float4*)(qg + ((size_t)(s0 + qi) * BATCH + b) * CDIM + h * HCDIM + dc);
        Qs[(dc + 0) * 64 + qi] = qv.x * 0.125f;
        Qs[(dc + 1) * 64 + qi] = qv.y * 0.125f;
        Qs[(dc + 2) * 64 + qi] = qv.z * 0.125f;
        Qs[(dc + 3) * 64 + qi] = qv.w * 0.125f;
    }

    float acc[4][4] = {};
    float mrow[4], lrow[4];
    #pragma unroll
    for (int i = 0; i < 4; i++) { mrow[i] = -INFINITY; lrow[i] = 0.0f; }

    const int ntile = (Teff + 63) >> 6;
    for (int kt = 0; kt < ntile; kt++) {
        const int t0 = kt << 6;
        __syncthreads();  // protect Ks/Vs (prev PV reads) before overwrite; covers Q stores on iter 0

        // Assemble K (transposed) and V tiles from memory / new-kv / zero
        for (int c = tid; c < 1024; c += 256) {
            int kj = c >> 4;
            int dc = (c & 15) << 2;
            int t = t0 + kj;
            float4 kv = make_float4(0.f, 0.f, 0.f, 0.f);
            float4 vv = make_float4(0.f, 0.f, 0.f, 0.f);
            if (t < L) {
                const float* bp = memkv + (((size_t)t * BATCH + b) * NHEAD + h) * (2 * HCDIM);
                kv = *(const float4*)(bp + dc);
                vv = *(const float4*)(bp + HCDIM + dc);
            } else if (t < Teff) {
                int j = t - L;
                kv = *(const float4*)(kg + ((size_t)j * BATCH + b) * CDIM + h * HCDIM + dc);
                vv = *(const float4*)(vg + ((size_t)j * BATCH + b) * CDIM + h * HCDIM + dc);
            }
            Ks[(dc + 0) * 65 + kj] = kv.x;
            Ks[(dc + 1) * 65 + kj] = kv.y;
            Ks[(dc + 2) * 65 + kj] = kv.z;
            Ks[(dc + 3) * 65 + kj] = kv.w;
            *(float4*)(Vs + kj * 64 + dc) = vv;
        }
        __syncthreads();

        // S = Q K^T  (q pre-scaled)
        float sv[4][4] = {};
        #pragma unroll 16
        for (int d = 0; d < 64; d++) {
            float4 a = *(const float4*)(Qs + d * 64 + (ty << 2));
            float k0v = Ks[d * 65 + (tx << 2) + 0];
            float k1v = Ks[d * 65 + (tx << 2) + 1];
            float k2v = Ks[d * 65 + (tx << 2) + 2];
            float k3v = Ks[d * 65 + (tx << 2) + 3];
            sv[0][0] += a.x * k0v; sv[0][1] += a.x * k1v; sv[0][2] += a.x * k2v; sv[0][3] += a.x * k3v;
            sv[1][0] += a.y * k0v; sv[1][1] += a.y * k1v; sv[1][2] += a.y * k2v; sv[1][3] += a.y * k3v;
            sv[2][0] += a.z * k0v; sv[2][1] += a.z * k1v; sv[2][2] += a.z * k2v; sv[2][3] += a.z * k3v;
            sv[3][0] += a.w * k0v; sv[3][1] += a.w * k1v; sv[3][2] += a.w * k2v; sv[3][3] += a.w * k3v;
        }

        // Masking: t >= Teff -> -inf; new region -> user mask lookup (all-False here)
        #pragma unroll
        for (int j = 0; j < 4; j++) {
            int t = t0 + (tx << 2) + j;
            if (t >= Teff) {
                #pragma unroll
                for (int i = 0; i < 4; i++) sv[i][j] = -INFINITY;
            } else if (t >= L) {
                int jn = t - L;
                #pragma unroll
                for (int i = 0; i < 4; i++) {
                    int srow = s0 + (ty << 2) + i;
                    if (mask[((size_t)srow * QS + jn) * BATCH + b]) sv[i][j] = -INFINITY;
                }
            }
        }

        // Online softmax per query row (row spread across 16 lanes, xor-reduce)
        #pragma unroll
        for (int i = 0; i < 4; i++) {
            float rm = fmaxf(fmaxf(sv[i][0], sv[i][1]), fmaxf(sv[i][2], sv[i][3]));
            #pragma unroll
            for (int o = 8; o > 0; o >>= 1) rm = fmaxf(rm, __shfl_xor_sync(0xffffffffu, rm, o));
            float mn = fmaxf(mrow[i], rm);
            float factor = (mn == -INFINITY) ? 1.0f : __expf(mrow[i] - mn);
            float rs = 0.0f;
            #pragma unroll
            for (int j = 0; j < 4; j++) {
                float p = (mn == -INFINITY) ? 0.0f : __expf(sv[i][j] - mn);
                sv[i][j] = p;
                rs += p;
            }
            #pragma unroll
            for (int o = 8; o > 0; o >>= 1) rs += __shfl_xor_sync(0xffffffffu, rs, o);
            lrow[i] = lrow[i] * factor + rs;
            mrow[i] = mn;
            #pragma unroll
            for (int j = 0; j < 4; j++) acc[i][j] *= factor;
        }

        __syncthreads();  // all S reads of Ks done before overwriting with P
        #pragma unroll
        for (int i = 0; i < 4; i++)
            #pragma unroll
            for (int j = 0; j < 4; j++)
                Ks[((tx << 2) + j) * 65 + (ty << 2) + i] = sv[i][j];  // Ps[kj][qi]
        __syncthreads();

        // O += P V
        #pragma unroll 16
        for (int kj = 0; kj < 64; kj++) {
            float p0 = Ks[kj * 65 + (ty << 2) + 0];
            float p1 = Ks[kj * 65 + (ty << 2) + 1];
            float p2 = Ks[kj * 65 + (ty << 2) + 2];
            float p3 = Ks[kj * 65 + (ty << 2) + 3];
            float4 v = *(const float4*)(Vs + kj * 64 + (tx << 2));
            acc[0][0] += p0 * v.x; acc[0][1] += p0 * v.y; acc[0][2] += p0 * v.z; acc[0][3] += p0 * v.w;
            acc[1][0] += p1 * v.x; acc[1][1] += p1 * v.y; acc[1][2] += p1 * v.z; acc[1][3] += p1 * v.w;
            acc[2][0] += p2 * v.x; acc[2][1] += p2 * v.y; acc[2][2] += p2 * v.z; acc[2][3] += p2 * v.w;
            acc[3][0] += p3 * v.x; acc[3][1] += p3 * v.y; acc[3][2] += p3 * v.z; acc[3][3] += p3 * v.w;
        }
    }

    // Normalize and write x in [s][b][c] layout (all-masked rows -> 0, matches nan_to_num)
    #pragma unroll
    for (int i = 0; i < 4; i++) {
        float inv = (lrow[i] > 0.0f) ? 1.0f / lrow[i] : 0.0f;
        float* orow = xout + ((size_t)(s0 + (ty << 2) + i) * BATCH + b) * CDIM + h * HCDIM + (tx << 2);
        #pragma unroll
        for (int j = 0; j < 4; j++) orow[j] = acc[i][j] * inv;
    }
}

// ---------------------------------------------------------------------------
// Launch
// ---------------------------------------------------------------------------
extern "C" void kernel_launch(void* const* d_in, const int* in_sizes, int n_in,
                              void* d_out, int out_size)
{
    const float*         xq     = (const float*)d_in[0];
    const int*           pad    = (const int*)d_in[1];
    const unsigned char* mask   = (const unsigned char*)d_in[2];
    const int*           memlen = (const int*)d_in[3];
    const float*         memkv  = (const float*)d_in[4];
    const float* Wq = (const float*)d_in[5];  const float* bq = (const float*)d_in[6];
    const float* Wk = (const float*)d_in[7];  const float* bk = (const float*)d_in[8];
    const float* Wv = (const float*)d_in[9];  const float* bv = (const float*)d_in[10];
    const float* Wo = (const float*)d_in[11]; const float* bo = (const float*)d_in[12];
    float* out = (float*)d_out;

    float *gq, *gk, *gv, *gx;
    cudaGetSymbolAddress((void**)&gq, g_q);
    cudaGetSymbolAddress((void**)&gk, g_k);
    cudaGetSymbolAddress((void**)&gv, g_v);
    cudaGetSymbolAddress((void**)&gx, g_x);

    dim3 gg(CDIM / 64, NTOK / 64);  // (16, 64)
    gemm_nt_bias<<<gg, 256>>>(xq, Wq, bq, gq);
    gemm_nt_bias<<<gg, 256>>>(xq, Wk, bk, gk);
    gemm_nt_bias<<<gg, 256>>>(xq, Wv, bv, gv);

    const int smem_bytes = (64 * 64 + 64 * 65 + 64 * 64) * (int)sizeof(float);  // 49408
    cudaFuncSetAttribute(attn_kernel, cudaFuncAttributeMaxDynamicSharedMemorySize, smem_bytes);
    attn_kernel<<<dim3(QS / 64, BATCH * NHEAD), 256, smem_bytes>>>(
        gq, gk, gv, memkv, memlen, pad, mask, gx);

    gemm_nt_bias<<<gg, 256>>>(gx, Wo, bo, out);
}

// round 3
// speedup vs baseline: 2.0650x; 2.0650x over previous
#include <cuda_runtime.h>
#include <math.h>
#include <stdint.h>

// Problem constants
#define QS    512
#define BATCH 8
#define CDIM  1024
#define NHEAD 16
#define HCDIM 64
#define MMEM  1536
#define NTOK  (QS * BATCH)   // 4096

// Scratch (device globals: allocation-guard safe)
__device__ float g_q[NTOK * CDIM];
__device__ float g_k[NTOK * CDIM];
__device__ float g_v[NTOK * CDIM];
__device__ float g_x[NTOK * CDIM];

__device__ __forceinline__ uint32_t f2tf32(float f) {
    uint32_t u;
    asm("cvt.rna.tf32.f32 %0, %1;" : "=r"(u) : "f"(f));
    return u;
}

// ---------------------------------------------------------------------------
// TF32 tensor-core GEMM: out[n][o] = sum_k A[n][k] * W[o][k] + bias[o]
// N = 4096, K = 1024, O = 1024.
// Block tile 128(n) x 128(o), k-chunk 32, 8 warps in 2x4 -> warp tile 64x32.
// mma.sync.m16n8k8.row.col tf32. Smem rows padded to 36 floats (conflict-free
// fragment loads: bank = (4*g + tig) mod 32, all distinct within a warp).
// ---------------------------------------------------------------------------
__global__ __launch_bounds__(256) void gemm_tf32_nt_bias(
    const float* __restrict__ A, const float* __restrict__ W,
    const float* __restrict__ bias, float* __restrict__ out)
{
    __shared__ uint32_t As[128 * 36];
    __shared__ uint32_t Ws[128 * 36];

    const int tid  = threadIdx.x;
    const int lane = tid & 31;
    const int warp = tid >> 5;
    const int g    = lane >> 2;   // groupID 0..7
    const int tig  = lane & 3;    // thread-in-group 0..3

    const int wm = (warp >> 2) * 64;  // warp m offset (0 or 64)
    const int wn = (warp & 3) * 32;   // warp n offset (0,32,64,96)

    const int n0 = blockIdx.y << 7;
    const int o0 = blockIdx.x << 7;

    const int lrow = tid >> 3;        // loader row 0..31 (4 passes of 32)
    const int lcol = (tid & 7) << 2;  // loader k offset 0..28

    float c[4][4][4];  // [mi][ni][frag]
    #pragma unroll
    for (int mi = 0; mi < 4; mi++)
        #pragma unroll
        for (int ni = 0; ni < 4; ni++)
            #pragma unroll
            for (int r = 0; r < 4; r++) c[mi][ni][r] = 0.0f;

    for (int k0 = 0; k0 < CDIM; k0 += 32) {
        #pragma unroll
        for (int p = 0; p < 4; p++) {
            int r = lrow + (p << 5);
            float4 av = *(const float4*)(A + (size_t)(n0 + r) * CDIM + k0 + lcol);
            As[r * 36 + lcol + 0] = f2tf32(av.x);
            As[r * 36 + lcol + 1] = f2tf32(av.y);
            As[r * 36 + lcol + 2] = f2tf32(av.z);
            As[r * 36 + lcol + 3] = f2tf32(av.w);
            float4 wv = *(const float4*)(W + (size_t)(o0 + r) * CDIM + k0 + lcol);
            Ws[r * 36 + lcol + 0] = f2tf32(wv.x);
            Ws[r * 36 + lcol + 1] = f2tf32(wv.y);
            Ws[r * 36 + lcol + 2] = f2tf32(wv.z);
            Ws[r * 36 + lcol + 3] = f2tf32(wv.w);
        }
        __syncthreads();

        #pragma unroll
        for (int ks = 0; ks < 4; ks++) {
            const int kk = ks << 3;
            uint32_t a[4][4], b[4][2];
            #pragma unroll
            for (int mi = 0; mi < 4; mi++) {
                const uint32_t* ap = As + (wm + (mi << 4) + g) * 36 + kk + tig;
                a[mi][0] = ap[0];
                a[mi][1] = ap[8 * 36];
                a[mi][2] = ap[4];
                a[mi][3] = ap[8 * 36 + 4];
            }
            #pragma unroll
            for (int ni = 0; ni < 4; ni++) {
                const uint32_t* bp = Ws + (wn + (ni << 3) + g) * 36 + kk + tig;
                b[ni][0] = bp[0];
                b[ni][1] = bp[4];
            }
            #pragma unroll
            for (int mi = 0; mi < 4; mi++)
                #pragma unroll
                for (int ni = 0; ni < 4; ni++) {
                    asm volatile(
                        "mma.sync.aligned.m16n8k8.row.col.f32.tf32.tf32.f32 "
                        "{%0,%1,%2,%3}, {%4,%5,%6,%7}, {%8,%9}, {%0,%1,%2,%3};"
                        : "+f"(c[mi][ni][0]), "+f"(c[mi][ni][1]),
                          "+f"(c[mi][ni][2]), "+f"(c[mi][ni][3])
                        : "r"(a[mi][0]), "r"(a[mi][1]), "r"(a[mi][2]), "r"(a[mi][3]),
                          "r"(b[ni][0]), "r"(b[ni][1]));
                }
        }
        __syncthreads();
    }

    // Epilogue: c0,c1 -> (row g, cols 2tig,2tig+1); c2,c3 -> row g+8
    #pragma unroll
    for (int mi = 0; mi < 4; mi++) {
        int row = n0 + wm + (mi << 4) + g;
        #pragma unroll
        for (int ni = 0; ni < 4; ni++) {
            int col = o0 + wn + (ni << 3) + (tig << 1);
            float b0 = bias[col], b1 = bias[col + 1];
            float2 v0 = make_float2(c[mi][ni][0] + b0, c[mi][ni][1] + b1);
            float2 v1 = make_float2(c[mi][ni][2] + b0, c[mi][ni][3] + b1);
            *(float2*)(out + (size_t)row * CDIM + col) = v0;
            *(float2*)(out + (size_t)(row + 8) * CDIM + col) = v1;
        }
    }
}

// ---------------------------------------------------------------------------
// Flash-attention over the combined (memory ++ new) KV sequence.
// Grid: (QS/64, BATCH*NHEAD). Block: 256 threads, 64q x 64k tiles.
// ---------------------------------------------------------------------------
__global__ __launch_bounds__(256) void attn_kernel(
    const float* __restrict__ qg, const float* __restrict__ kg,
    const float* __restrict__ vg, const float* __restrict__ memkv,
    const int* __restrict__ memlen, const int* __restrict__ padv,
    const unsigned char* __restrict__ mask, float* __restrict__ xout)
{
    extern __shared__ float sm[];
    float* Qs = sm;                 // [d][qi]  64x64, stride 64
    float* Ks = sm + 64 * 64;       // [d][kj]  64x65; reused as Ps[kj][qi]
    float* Vs = Ks + 64 * 65;       // [kj][c]  64x64

    const int tid = threadIdx.x;
    const int tx = tid & 15;
    const int ty = tid >> 4;
    const int s0 = blockIdx.x << 6;
    const int b  = blockIdx.y >> 4;
    const int h  = blockIdx.y & 15;
    const int L  = memlen[b];
    const int P  = padv[b];
    const int Teff = L + P;

    for (int c = tid; c < 1024; c += 256) {
        int qi = c >> 4;
        int dc = (c & 15) << 2;
        float4 qv = *(const float4*)(qg + ((size_t)(s0 + qi) * BATCH + b) * CDIM + h * HCDIM + dc);
        Qs[(dc + 0) * 64 + qi] = qv.x * 0.125f;
        Qs[(dc + 1) * 64 + qi] = qv.y * 0.125f;
        Qs[(dc + 2) * 64 + qi] = qv.z * 0.125f;
        Qs[(dc + 3) * 64 + qi] = qv.w * 0.125f;
    }

    float acc[4][4] = {};
    float mrow[4], lrow[4];
    #pragma unroll
    for (int i = 0; i < 4; i++) { mrow[i] = -INFINITY; lrow[i] = 0.0f; }

    const int ntile = (Teff + 63) >> 6;
    for (int kt = 0; kt < ntile; kt++) {
        const int t0 = kt << 6;
        __syncthreads();

        for (int c = tid; c < 1024; c += 256) {
            int kj = c >> 4;
            int dc = (c & 15) << 2;
            int t = t0 + kj;
            float4 kv = make_float4(0.f, 0.f, 0.f, 0.f);
            float4 vv = make_float4(0.f, 0.f, 0.f, 0.f);
            if (t < L) {
                const float* bp = memkv + (((size_t)t * BATCH + b) * NHEAD + h) * (2 * HCDIM);
                kv = *(const float4*)(bp + dc);
                vv = *(const float4*)(bp + HCDIM + dc);
            } else if (t < Teff) {
                int j = t - L;
                kv = *(const float4*)(kg + ((size_t)j * BATCH + b) * CDIM + h * HCDIM + dc);
                vv = *(const float4*)(vg + ((size_t)j * BATCH + b) * CDIM + h * HCDIM + dc);
            }
            Ks[(dc + 0) * 65 + kj] = kv.x;
            Ks[(dc + 1) * 65 + kj] = kv.y;
            Ks[(dc + 2) * 65 + kj] = kv.z;
            Ks[(dc + 3) * 65 + kj] = kv.w;
            *(float4*)(Vs + kj * 64 + dc) = vv;
        }
        __syncthreads();

        float sv[4][4] = {};
        #pragma unroll 16
        for (int d = 0; d < 64; d++) {
            float4 a = *(const float4*)(Qs + d * 64 + (ty << 2));
            float k0v = Ks[d * 65 + (tx << 2) + 0];
            float k1v = Ks[d * 65 + (tx << 2) + 1];
            float k2v = Ks[d * 65 + (tx << 2) + 2];
            float k3v = Ks[d * 65 + (tx << 2) + 3];
            sv[0][0] += a.x * k0v; sv[0][1] += a.x * k1v; sv[0][2] += a.x * k2v; sv[0][3] += a.x * k3v;
            sv[1][0] += a.y * k0v; sv[1][1] += a.y * k1v; sv[1][2] += a.y * k2v; sv[1][3] += a.y * k3v;
            sv[2][0] += a.z * k0v; sv[2][1] += a.z * k1v; sv[2][2] += a.z * k2v; sv[2][3] += a.z * k3v;
            sv[3][0] += a.w * k0v; sv[3][1] += a.w * k1v; sv[3][2] += a.w * k2v; sv[3][3] += a.w * k3v;
        }

        #pragma unroll
        for (int j = 0; j < 4; j++) {
            int t = t0 + (tx << 2) + j;
            if (t >= Teff) {
                #pragma unroll
                for (int i = 0; i < 4; i++) sv[i][j] = -INFINITY;
            } else if (t >= L) {
                int jn = t - L;
                #pragma unroll
                for (int i = 0; i < 4; i++) {
                    int srow = s0 + (ty << 2) + i;
                    if (mask[((size_t)srow * QS + jn) * BATCH + b]) sv[i][j] = -INFINITY;
                }
            }
        }

        #pragma unroll
        for (int i = 0; i < 4; i++) {
            float rm = fmaxf(fmaxf(sv[i][0], sv[i][1]), fmaxf(sv[i][2], sv[i][3]));
            #pragma unroll
            for (int o = 8; o > 0; o >>= 1) rm = fmaxf(rm, __shfl_xor_sync(0xffffffffu, rm, o));
            float mn = fmaxf(mrow[i], rm);
            float factor = (mn == -INFINITY) ? 1.0f : __expf(mrow[i] - mn);
            float rs = 0.0f;
            #pragma unroll
            for (int j = 0; j < 4; j++) {
                float p = (mn == -INFINITY) ? 0.0f : __expf(sv[i][j] - mn);
                sv[i][j] = p;
                rs += p;
            }
            #pragma unroll
            for (int o = 8; o > 0; o >>= 1) rs += __shfl_xor_sync(0xffffffffu, rs, o);
            lrow[i] = lrow[i] * factor + rs;
            mrow[i] = mn;
            #pragma unroll
            for (int j = 0; j < 4; j++) acc[i][j] *= factor;
        }

        __syncthreads();
        #pragma unroll
        for (int i = 0; i < 4; i++)
            #pragma unroll
            for (int j = 0; j < 4; j++)
                Ks[((tx << 2) + j) * 65 + (ty << 2) + i] = sv[i][j];
        __syncthreads();

        #pragma unroll 16
        for (int kj = 0; kj < 64; kj++) {
            float p0 = Ks[kj * 65 + (ty << 2) + 0];
            float p1 = Ks[kj * 65 + (ty << 2) + 1];
            float p2 = Ks[kj * 65 + (ty << 2) + 2];
            float p3 = Ks[kj * 65 + (ty << 2) + 3];
            float4 v = *(const float4*)(Vs + kj * 64 + (tx << 2));
            acc[0][0] += p0 * v.x; acc[0][1] += p0 * v.y; acc[0][2] += p0 * v.z; acc[0][3] += p0 * v.w;
            acc[1][0] += p1 * v.x; acc[1][1] += p1 * v.y; acc[1][2] += p1 * v.z; acc[1][3] += p1 * v.w;
            acc[2][0] += p2 * v.x; acc[2][1] += p2 * v.y; acc[2][2] += p2 * v.z; acc[2][3] += p2 * v.w;
            acc[3][0] += p3 * v.x; acc[3][1] += p3 * v.y; acc[3][2] += p3 * v.z; acc[3][3] += p3 * v.w;
        }
    }

    #pragma unroll
    for (int i = 0; i < 4; i++) {
        float inv = (lrow[i] > 0.0f) ? 1.0f / lrow[i] : 0.0f;
        float* orow = xout + ((size_t)(s0 + (ty << 2) + i) * BATCH + b) * CDIM + h * HCDIM + (tx << 2);
        #pragma unroll
        for (int j = 0; j < 4; j++) orow[j] = acc[i][j] * inv;
    }
}

// ---------------------------------------------------------------------------
// Launch
// ---------------------------------------------------------------------------
extern "C" void kernel_launch(void* const* d_in, const int* in_sizes, int n_in,
                              void* d_out, int out_size)
{
    const float*         xq     = (const float*)d_in[0];
    const int*           pad    = (const int*)d_in[1];
    const unsigned char* mask   = (const unsigned char*)d_in[2];
    const int*           memlen = (const int*)d_in[3];
    const float*         memkv  = (const float*)d_in[4];
    const float* Wq = (const float*)d_in[5];  const float* bq = (const float*)d_in[6];
    const float* Wk = (const float*)d_in[7];  const float* bk = (const float*)d_in[8];
    const float* Wv = (const float*)d_in[9];  const float* bv = (const float*)d_in[10];
    const float* Wo = (const float*)d_in[11]; const float* bo = (const float*)d_in[12];
    float* out = (float*)d_out;

    float *gq, *gk, *gv, *gx;
    cudaGetSymbolAddress((void**)&gq, g_q);
    cudaGetSymbolAddress((void**)&gk, g_k);
    cudaGetSymbolAddress((void**)&gv, g_v);
    cudaGetSymbolAddress((void**)&gx, g_x);

    dim3 gg(CDIM / 128, NTOK / 128);  // (8, 32)
    gemm_tf32_nt_bias<<<gg, 256>>>(xq, Wq, bq, gq);
    gemm_tf32_nt_bias<<<gg, 256>>>(xq, Wk, bk, gk);
    gemm_tf32_nt_bias<<<gg, 256>>>(xq, Wv, bv, gv);

    const int smem_bytes = (64 * 64 + 64 * 65 + 64 * 64) * (int)sizeof(float);  // 49408
    cudaFuncSetAttribute(attn_kernel, cudaFuncAttributeMaxDynamicSharedMemorySize, smem_bytes);
    attn_kernel<<<dim3(QS / 64, BATCH * NHEAD), 256, smem_bytes>>>(
        gq, gk, gv, memkv, memlen, pad, mask, gx);

    gemm_tf32_nt_bias<<<gg, 256>>>(gx, Wo, bo, out);
}

// round 4
// speedup vs baseline: 2.7607x; 1.3369x over previous
#include <cuda_runtime.h>
#include <math.h>
#include <stdint.h>

// Problem constants
#define QS    512
#define BATCH 8
#define CDIM  1024
#define NHEAD 16
#define HCDIM 64
#define MMEM  1536
#define NTOK  (QS * BATCH)   // 4096

// Scratch (device globals: allocation-guard safe)
__device__ float g_q[NTOK * CDIM];
__device__ float g_k[NTOK * CDIM];
__device__ float g_v[NTOK * CDIM];
__device__ float g_x[NTOK * CDIM];

__device__ __forceinline__ uint32_t f2tf32(float f) {
    uint32_t u;
    asm("cvt.rna.tf32.f32 %0, %1;" : "=r"(u) : "f"(f));
    return u;
}

__device__ __forceinline__ void mma_tf32(float c[4],
    uint32_t a0, uint32_t a1, uint32_t a2, uint32_t a3,
    uint32_t b0, uint32_t b1)
{
    asm volatile(
        "mma.sync.aligned.m16n8k8.row.col.f32.tf32.tf32.f32 "
        "{%0,%1,%2,%3}, {%4,%5,%6,%7}, {%8,%9}, {%0,%1,%2,%3};"
        : "+f"(c[0]), "+f"(c[1]), "+f"(c[2]), "+f"(c[3])
        : "r"(a0), "r"(a1), "r"(a2), "r"(a3), "r"(b0), "r"(b1));
}

// ---------------------------------------------------------------------------
// TF32 tensor-core GEMM: out[n][o] = sum_k A[n][k] * W[o][k] + bias[o]
// Block tile 128x128, k-chunk 32, 8 warps (2x4), warp tile 64x32.
// ---------------------------------------------------------------------------
__global__ __launch_bounds__(256) void gemm_tf32_nt_bias(
    const float* __restrict__ A, const float* __restrict__ W,
    const float* __restrict__ bias, float* __restrict__ out)
{
    __shared__ uint32_t As[128 * 36];
    __shared__ uint32_t Ws[128 * 36];

    const int tid  = threadIdx.x;
    const int lane = tid & 31;
    const int warp = tid >> 5;
    const int g    = lane >> 2;
    const int tig  = lane & 3;

    const int wm = (warp >> 2) * 64;
    const int wn = (warp & 3) * 32;

    const int n0 = blockIdx.y << 7;
    const int o0 = blockIdx.x << 7;

    const int lrow = tid >> 3;
    const int lcol = (tid & 7) << 2;

    float c[4][4][4];
    #pragma unroll
    for (int mi = 0; mi < 4; mi++)
        #pragma unroll
        for (int ni = 0; ni < 4; ni++)
            #pragma unroll
            for (int r = 0; r < 4; r++) c[mi][ni][r] = 0.0f;

    for (int k0 = 0; k0 < CDIM; k0 += 32) {
        #pragma unroll
        for (int p = 0; p < 4; p++) {
            int r = lrow + (p << 5);
            float4 av = *(const float4*)(A + (size_t)(n0 + r) * CDIM + k0 + lcol);
            As[r * 36 + lcol + 0] = f2tf32(av.x);
            As[r * 36 + lcol + 1] = f2tf32(av.y);
            As[r * 36 + lcol + 2] = f2tf32(av.z);
            As[r * 36 + lcol + 3] = f2tf32(av.w);
            float4 wv = *(const float4*)(W + (size_t)(o0 + r) * CDIM + k0 + lcol);
            Ws[r * 36 + lcol + 0] = f2tf32(wv.x);
            Ws[r * 36 + lcol + 1] = f2tf32(wv.y);
            Ws[r * 36 + lcol + 2] = f2tf32(wv.z);
            Ws[r * 36 + lcol + 3] = f2tf32(wv.w);
        }
        __syncthreads();

        #pragma unroll
        for (int ks = 0; ks < 4; ks++) {
            const int kk = ks << 3;
            uint32_t a[4][4], b[4][2];
            #pragma unroll
            for (int mi = 0; mi < 4; mi++) {
                const uint32_t* ap = As + (wm + (mi << 4) + g) * 36 + kk + tig;
                a[mi][0] = ap[0];
                a[mi][1] = ap[8 * 36];
                a[mi][2] = ap[4];
                a[mi][3] = ap[8 * 36 + 4];
            }
            #pragma unroll
            for (int ni = 0; ni < 4; ni++) {
                const uint32_t* bp = Ws + (wn + (ni << 3) + g) * 36 + kk + tig;
                b[ni][0] = bp[0];
                b[ni][1] = bp[4];
            }
            #pragma unroll
            for (int mi = 0; mi < 4; mi++)
                #pragma unroll
                for (int ni = 0; ni < 4; ni++)
                    mma_tf32(c[mi][ni], a[mi][0], a[mi][1], a[mi][2], a[mi][3],
                             b[ni][0], b[ni][1]);
        }
        __syncthreads();
    }

    #pragma unroll
    for (int mi = 0; mi < 4; mi++) {
        int row = n0 + wm + (mi << 4) + g;
        #pragma unroll
        for (int ni = 0; ni < 4; ni++) {
            int col = o0 + wn + (ni << 3) + (tig << 1);
            float b0 = bias[col], b1 = bias[col + 1];
            float2 v0 = make_float2(c[mi][ni][0] + b0, c[mi][ni][1] + b1);
            float2 v1 = make_float2(c[mi][ni][2] + b0, c[mi][ni][3] + b1);
            *(float2*)(out + (size_t)row * CDIM + col) = v0;
            *(float2*)(out + (size_t)(row + 8) * CDIM + col) = v1;
        }
    }
}

// ---------------------------------------------------------------------------
// TF32 tensor-core flash attention over the combined (memory ++ new) KV.
// Grid: (QS/64, BATCH*NHEAD). Block: 128 threads (4 warps).
// Tile 64q x 64k; warp w owns q rows [16w, 16w+16).
// Smem rows padded to 68 u32 -> fragment bank = 4g+tig (conflict-free).
// ---------------------------------------------------------------------------
__global__ __launch_bounds__(128) void attn_tc_kernel(
    const float* __restrict__ qg, const float* __restrict__ kg,
    const float* __restrict__ vg, const float* __restrict__ memkv,
    const int* __restrict__ memlen, const int* __restrict__ padv,
    const unsigned char* __restrict__ mask, float* __restrict__ xout)
{
    extern __shared__ uint32_t smu[];
    uint32_t* Qs = smu;              // [qi][d]   64x68 (tf32, pre-scaled)
    uint32_t* Ks = Qs + 64 * 68;     // [kj][d]   64x68
    uint32_t* Vt = Ks + 64 * 68;     // [c][kj]   64x68 (V transposed)
    uint32_t* Ps = Vt + 64 * 68;     // [qi][kj]  64x68

    const int tid  = threadIdx.x;
    const int lane = tid & 31;
    const int warp = tid >> 5;       // 0..3
    const int g    = lane >> 2;      // 0..7
    const int tig  = lane & 3;       // 0..3

    const int s0 = blockIdx.x << 6;
    const int b  = blockIdx.y >> 4;
    const int h  = blockIdx.y & 15;
    const int L  = memlen[b];
    const int P  = padv[b];
    const int Teff = L + P;

    // Load Q tile: [qi][d], pre-scaled by 1/sqrt(64), tf32
    for (int i = tid; i < 1024; i += 128) {
        int qi = i >> 4;
        int dc = (i & 15) << 2;
        float4 qv = *(const float4*)(qg + ((size_t)(s0 + qi) * BATCH + b) * CDIM + h * HCDIM + dc);
        uint4 u;
        u.x = f2tf32(qv.x * 0.125f);
        u.y = f2tf32(qv.y * 0.125f);
        u.z = f2tf32(qv.z * 0.125f);
        u.w = f2tf32(qv.w * 0.125f);
        *(uint4*)(Qs + qi * 68 + dc) = u;
    }

    float oacc[8][4];
    #pragma unroll
    for (int ni = 0; ni < 8; ni++)
        #pragma unroll
        for (int r = 0; r < 4; r++) oacc[ni][r] = 0.0f;
    float mrow[2] = { -INFINITY, -INFINITY };
    float lrow[2] = { 0.0f, 0.0f };

    const int qrow0 = warp * 16 + g;   // rows qrow0, qrow0+8 in tile

    const int ntile = (Teff + 63) >> 6;
    for (int kt = 0; kt < ntile; kt++) {
        const int t0 = kt << 6;
        __syncthreads();  // prior PV reads of Vt done; covers Q stores on iter 0

        // Assemble K [kj][d] and V transposed [c][kj]
        for (int i = tid; i < 1024; i += 128) {
            int kj = i >> 4;
            int dc = (i & 15) << 2;
            int t = t0 + kj;
            float4 kv = make_float4(0.f, 0.f, 0.f, 0.f);
            float4 vv = make_float4(0.f, 0.f, 0.f, 0.f);
            if (t < L) {
                const float* bp = memkv + (((size_t)t * BATCH + b) * NHEAD + h) * (2 * HCDIM);
                kv = *(const float4*)(bp + dc);
                vv = *(const float4*)(bp + HCDIM + dc);
            } else if (t < Teff) {
                int j = t - L;
                kv = *(const float4*)(kg + ((size_t)j * BATCH + b) * CDIM + h * HCDIM + dc);
                vv = *(const float4*)(vg + ((size_t)j * BATCH + b) * CDIM + h * HCDIM + dc);
            }
            uint4 u;
            u.x = f2tf32(kv.x); u.y = f2tf32(kv.y); u.z = f2tf32(kv.z); u.w = f2tf32(kv.w);
            *(uint4*)(Ks + kj * 68 + dc) = u;
            Vt[(dc + 0) * 68 + kj] = f2tf32(vv.x);
            Vt[(dc + 1) * 68 + kj] = f2tf32(vv.y);
            Vt[(dc + 2) * 68 + kj] = f2tf32(vv.z);
            Vt[(dc + 3) * 68 + kj] = f2tf32(vv.w);
        }
        __syncthreads();

        // S = Q K^T (tensor cores). sv[ni]: rows qrow0/qrow0+8, cols ni*8+2tig{,+1}
        float sv[8][4];
        #pragma unroll
        for (int ni = 0; ni < 8; ni++)
            #pragma unroll
            for (int r = 0; r < 4; r++) sv[ni][r] = 0.0f;

        const uint32_t* qb = Qs + qrow0 * 68;
        #pragma unroll
        for (int ks = 0; ks < 8; ks++) {
            const int kk = ks << 3;
            uint32_t a0 = qb[kk + tig];
            uint32_t a1 = qb[8 * 68 + kk + tig];
            uint32_t a2 = qb[kk + tig + 4];
            uint32_t a3 = qb[8 * 68 + kk + tig + 4];
            #pragma unroll
            for (int ni = 0; ni < 8; ni++) {
                const uint32_t* bp = Ks + ((ni << 3) + g) * 68 + kk + tig;
                mma_tf32(sv[ni], a0, a1, a2, a3, bp[0], bp[4]);
            }
        }

        // Masking
        #pragma unroll
        for (int ni = 0; ni < 8; ni++) {
            #pragma unroll
            for (int cc = 0; cc < 2; cc++) {
                int t = t0 + (ni << 3) + (tig << 1) + cc;
                if (t >= Teff) {
                    sv[ni][cc] = -INFINITY;
                    sv[ni][2 + cc] = -INFINITY;
                } else if (t >= L) {
                    int jn = t - L;
                    int r0 = s0 + qrow0;
                    if (mask[((size_t)r0 * QS + jn) * BATCH + b]) sv[ni][cc] = -INFINITY;
                    if (mask[((size_t)(r0 + 8) * QS + jn) * BATCH + b]) sv[ni][2 + cc] = -INFINITY;
                }
            }
        }

        // Online softmax per row-half (row spread over 4 tig lanes)
        #pragma unroll
        for (int half = 0; half < 2; half++) {
            const int o0i = half << 1;
            float rm = -INFINITY;
            #pragma unroll
            for (int ni = 0; ni < 8; ni++)
                rm = fmaxf(rm, fmaxf(sv[ni][o0i], sv[ni][o0i + 1]));
            rm = fmaxf(rm, __shfl_xor_sync(0xffffffffu, rm, 1));
            rm = fmaxf(rm, __shfl_xor_sync(0xffffffffu, rm, 2));
            float mn = fmaxf(mrow[half], rm);
            float factor = (mn == -INFINITY) ? 1.0f : __expf(mrow[half] - mn);
            float rs = 0.0f;
            #pragma unroll
            for (int ni = 0; ni < 8; ni++) {
                #pragma unroll
                for (int cc = 0; cc < 2; cc++) {
                    float p = (mn == -INFINITY) ? 0.0f : __expf(sv[ni][o0i + cc] - mn);
                    sv[ni][o0i + cc] = p;
                    rs += p;
                }
            }
            rs += __shfl_xor_sync(0xffffffffu, rs, 1);
            rs += __shfl_xor_sync(0xffffffffu, rs, 2);
            lrow[half] = lrow[half] * factor + rs;
            mrow[half] = mn;
            #pragma unroll
            for (int ni = 0; ni < 8; ni++) {
                oacc[ni][o0i] *= factor;
                oacc[ni][o0i + 1] *= factor;
            }
        }

        // Store P to smem (own warp's rows only -> warp-local sync suffices)
        uint32_t* pb = Ps + qrow0 * 68;
        #pragma unroll
        for (int ni = 0; ni < 8; ni++) {
            int cix = (ni << 3) + (tig << 1);
            pb[cix]            = f2tf32(sv[ni][0]);
            pb[cix + 1]        = f2tf32(sv[ni][1]);
            pb[8 * 68 + cix]     = f2tf32(sv[ni][2]);
            pb[8 * 68 + cix + 1] = f2tf32(sv[ni][3]);
        }
        __syncwarp();

        // O += P V  (A = P [q][t], B = Vt [c][t])
        #pragma unroll
        for (int ks = 0; ks < 8; ks++) {
            const int kk = ks << 3;
            uint32_t a0 = pb[kk + tig];
            uint32_t a1 = pb[8 * 68 + kk + tig];
            uint32_t a2 = pb[kk + tig + 4];
            uint32_t a3 = pb[8 * 68 + kk + tig + 4];
            #pragma unroll
            for (int ni = 0; ni < 8; ni++) {
                const uint32_t* bp = Vt + ((ni << 3) + g) * 68 + kk + tig;
                mma_tf32(oacc[ni], a0, a1, a2, a3, bp[0], bp[4]);
            }
        }
    }

    // Normalize and write x[s][b][c] (all-masked rows -> 0)
    #pragma unroll
    for (int half = 0; half < 2; half++) {
        float inv = (lrow[half] > 0.0f) ? 1.0f / lrow[half] : 0.0f;
        int row = s0 + qrow0 + (half << 3);
        float* orow = xout + ((size_t)row * BATCH + b) * CDIM + h * HCDIM;
        #pragma unroll
        for (int ni = 0; ni < 8; ni++) {
            int col = (ni << 3) + (tig << 1);
            float2 v = make_float2(oacc[ni][(half << 1)] * inv,
                                   oacc[ni][(half << 1) + 1] * inv);
            *(float2*)(orow + col) = v;
        }
    }
}

// ---------------------------------------------------------------------------
// Launch
// ---------------------------------------------------------------------------
extern "C" void kernel_launch(void* const* d_in, const int* in_sizes, int n_in,
                              void* d_out, int out_size)
{
    const float*         xq     = (const float*)d_in[0];
    const int*           pad    = (const int*)d_in[1];
    const unsigned char* mask   = (const unsigned char*)d_in[2];
    const int*           memlen = (const int*)d_in[3];
    const float*         memkv  = (const float*)d_in[4];
    const float* Wq = (const float*)d_in[5];  const float* bq = (const float*)d_in[6];
    const float* Wk = (const float*)d_in[7];  const float* bk = (const float*)d_in[8];
    const float* Wv = (const float*)d_in[9];  const float* bv = (const float*)d_in[10];
    const float* Wo = (const float*)d_in[11]; const float* bo = (const float*)d_in[12];
    float* out = (float*)d_out;

    float *gq, *gk, *gv, *gx;
    cudaGetSymbolAddress((void**)&gq, g_q);
    cudaGetSymbolAddress((void**)&gk, g_k);
    cudaGetSymbolAddress((void**)&gv, g_v);
    cudaGetSymbolAddress((void**)&gx, g_x);

    dim3 gg(CDIM / 128, NTOK / 128);  // (8, 32)
    gemm_tf32_nt_bias<<<gg, 256>>>(xq, Wq, bq, gq);
    gemm_tf32_nt_bias<<<gg, 256>>>(xq, Wk, bk, gk);
    gemm_tf32_nt_bias<<<gg, 256>>>(xq, Wv, bv, gv);

    const int smem_bytes = 4 * 64 * 68 * (int)sizeof(uint32_t);  // 69632
    cudaFuncSetAttribute(attn_tc_kernel, cudaFuncAttributeMaxDynamicSharedMemorySize, smem_bytes);
    attn_tc_kernel<<<dim3(QS / 64, BATCH * NHEAD), 128, smem_bytes>>>(
        gq, gk, gv, memkv, memlen, pad, mask, gx);

    gemm_tf32_nt_bias<<<gg, 256>>>(gx, Wo, bo, out);
}

// round 5
// speedup vs baseline: 3.9368x; 1.4260x over previous
#include <cuda_runtime.h>
#include <math.h>
#include <stdint.h>

// Problem constants
#define QS    512
#define BATCH 8
#define CDIM  1024
#define NHEAD 16
#define HCDIM 64
#define MMEM  1536
#define NTOK  (QS * BATCH)   // 4096

// Scratch (device globals: allocation-guard safe)
__device__ float g_q[NTOK * CDIM];
__device__ float g_k[NTOK * CDIM];
__device__ float g_v[NTOK * CDIM];
__device__ float g_x[NTOK * CDIM];

__device__ __forceinline__ uint32_t f2tf32(float f) {
    uint32_t u;
    asm("cvt.rna.tf32.f32 %0, %1;" : "=r"(u) : "f"(f));
    return u;
}

__device__ __forceinline__ void mma_tf32(float c[4],
    uint32_t a0, uint32_t a1, uint32_t a2, uint32_t a3,
    uint32_t b0, uint32_t b1)
{
    asm volatile(
        "mma.sync.aligned.m16n8k8.row.col.f32.tf32.tf32.f32 "
        "{%0,%1,%2,%3}, {%4,%5,%6,%7}, {%8,%9}, {%0,%1,%2,%3};"
        : "+f"(c[0]), "+f"(c[1]), "+f"(c[2]), "+f"(c[3])
        : "r"(a0), "r"(a1), "r"(a2), "r"(a3), "r"(b0), "r"(b1));
}

__device__ __forceinline__ void cp16(uint32_t dst, const void* src, int sz) {
    asm volatile("cp.async.cg.shared.global [%0], [%1], 16, %2;"
                 :: "r"(dst), "l"(src), "r"(sz));
}
__device__ __forceinline__ void cp_commit() {
    asm volatile("cp.async.commit_group;");
}
__device__ __forceinline__ void cp_wait0() {
    asm volatile("cp.async.wait_group 0;");
}
__device__ __forceinline__ void cp_wait1() {
    asm volatile("cp.async.wait_group 1;");
}

// ---------------------------------------------------------------------------
// TF32 tensor-core GEMM: out[n][o] = sum_k A[n][k] * W[o][k] + bias[o]
// Block tile 128x128, k-chunk 32, 8 warps (2x4), warp tile 64x32.
// Register double-buffered global loads (keeps cvt.rna precision).
// ---------------------------------------------------------------------------
__global__ __launch_bounds__(256) void gemm_tf32_nt_bias(
    const float* __restrict__ A, const float* __restrict__ W,
    const float* __restrict__ bias, float* __restrict__ out)
{
    __shared__ uint32_t As[128 * 36];
    __shared__ uint32_t Ws[128 * 36];

    const int tid  = threadIdx.x;
    const int lane = tid & 31;
    const int warp = tid >> 5;
    const int g    = lane >> 2;
    const int tig  = lane & 3;

    const int wm = (warp >> 2) * 64;
    const int wn = (warp & 3) * 32;

    const int n0 = blockIdx.y << 7;
    const int o0 = blockIdx.x << 7;

    const int lrow = tid >> 3;
    const int lcol = (tid & 7) << 2;

    float c[4][4][4];
    #pragma unroll
    for (int mi = 0; mi < 4; mi++)
        #pragma unroll
        for (int ni = 0; ni < 4; ni++)
            #pragma unroll
            for (int r = 0; r < 4; r++) c[mi][ni][r] = 0.0f;

    float4 ra[4], rw[4];
    #pragma unroll
    for (int p = 0; p < 4; p++) {
        int r = lrow + (p << 5);
        ra[p] = *(const float4*)(A + (size_t)(n0 + r) * CDIM + lcol);
        rw[p] = *(const float4*)(W + (size_t)(o0 + r) * CDIM + lcol);
    }

    for (int k0 = 0; k0 < CDIM; k0 += 32) {
        #pragma unroll
        for (int p = 0; p < 4; p++) {
            int r = lrow + (p << 5);
            As[r * 36 + lcol + 0] = f2tf32(ra[p].x);
            As[r * 36 + lcol + 1] = f2tf32(ra[p].y);
            As[r * 36 + lcol + 2] = f2tf32(ra[p].z);
            As[r * 36 + lcol + 3] = f2tf32(ra[p].w);
            Ws[r * 36 + lcol + 0] = f2tf32(rw[p].x);
            Ws[r * 36 + lcol + 1] = f2tf32(rw[p].y);
            Ws[r * 36 + lcol + 2] = f2tf32(rw[p].z);
            Ws[r * 36 + lcol + 3] = f2tf32(rw[p].w);
        }
        __syncthreads();

        if (k0 + 32 < CDIM) {
            #pragma unroll
            for (int p = 0; p < 4; p++) {
                int r = lrow + (p << 5);
                ra[p] = *(const float4*)(A + (size_t)(n0 + r) * CDIM + k0 + 32 + lcol);
                rw[p] = *(const float4*)(W + (size_t)(o0 + r) * CDIM + k0 + 32 + lcol);
            }
        }

        #pragma unroll
        for (int ks = 0; ks < 4; ks++) {
            const int kk = ks << 3;
            uint32_t a[4][4], b[4][2];
            #pragma unroll
            for (int mi = 0; mi < 4; mi++) {
                const uint32_t* ap = As + (wm + (mi << 4) + g) * 36 + kk + tig;
                a[mi][0] = ap[0];
                a[mi][1] = ap[8 * 36];
                a[mi][2] = ap[4];
                a[mi][3] = ap[8 * 36 + 4];
            }
            #pragma unroll
            for (int ni = 0; ni < 4; ni++) {
                const uint32_t* bp = Ws + (wn + (ni << 3) + g) * 36 + kk + tig;
                b[ni][0] = bp[0];
                b[ni][1] = bp[4];
            }
            #pragma unroll
            for (int mi = 0; mi < 4; mi++)
                #pragma unroll
                for (int ni = 0; ni < 4; ni++)
                    mma_tf32(c[mi][ni], a[mi][0], a[mi][1], a[mi][2], a[mi][3],
                             b[ni][0], b[ni][1]);
        }
        __syncthreads();
    }

    #pragma unroll
    for (int mi = 0; mi < 4; mi++) {
        int row = n0 + wm + (mi << 4) + g;
        #pragma unroll
        for (int ni = 0; ni < 4; ni++) {
            int col = o0 + wn + (ni << 3) + (tig << 1);
            float b0 = bias[col], b1 = bias[col + 1];
            float2 v0 = make_float2(c[mi][ni][0] + b0, c[mi][ni][1] + b1);
            float2 v1 = make_float2(c[mi][ni][2] + b0, c[mi][ni][3] + b1);
            *(float2*)(out + (size_t)row * CDIM + col) = v0;
            *(float2*)(out + (size_t)(row + 8) * CDIM + col) = v1;
        }
    }
}

// ---------------------------------------------------------------------------
// TF32 tensor-core flash attention, 2-stage cp.async pipelined KV gather.
// Grid: (QS/64, BATCH*NHEAD). Block: 128 threads (4 warps), 64q x 64k tiles.
// K stored [kj][d] stride 68 (frag bank 4g+tig). V stored [t][c] stride 72
// (frag bank 8tig+g) -- both conflict-free, stores coalesced via cp.async.
// Q lives in register fragments; P converted C-frag -> A-frag via shuffles.
// ---------------------------------------------------------------------------
#define KSTR 68
#define VSTR 72
#define KV_WORDS (64 * KSTR + 64 * VSTR)   // one stage: 8960 words

__global__ __launch_bounds__(128) void attn_tc_kernel(
    const float* __restrict__ qg, const float* __restrict__ kg,
    const float* __restrict__ vg, const float* __restrict__ memkv,
    const int* __restrict__ memlen, const int* __restrict__ padv,
    const unsigned char* __restrict__ mask, float* __restrict__ xout)
{
    extern __shared__ uint32_t smu[];   // 2 * KV_WORDS = 17920 words = 71680 B
    const uint32_t smem_base = (uint32_t)__cvta_generic_to_shared(smu);

    const int tid  = threadIdx.x;
    const int lane = tid & 31;
    const int warp = tid >> 5;       // 0..3
    const int g    = lane >> 2;      // 0..7
    const int tig  = lane & 3;       // 0..3

    const int s0 = blockIdx.x << 6;
    const int b  = blockIdx.y >> 4;
    const int h  = blockIdx.y & 15;
    const int L  = memlen[b];
    const int P  = padv[b];
    const int Teff = L + P;
    const int qrow0 = warp * 16 + g;

    // ---- Stage Q through smem (buffer 0), then into register fragments ----
    {
        float* Qst = (float*)smu;   // [qi][d] stride 68
        for (int i = tid; i < 1024; i += 128) {
            int qi = i >> 4;
            int dc = (i & 15) << 2;
            float4 qv = *(const float4*)(qg + ((size_t)(s0 + qi) * BATCH + b) * CDIM + h * HCDIM + dc);
            *(float4*)(Qst + qi * KSTR + dc) = qv;
        }
    }
    __syncthreads();

    uint32_t qf[8][4];
    {
        const float* q0 = (const float*)smu + qrow0 * KSTR;
        const float* q8 = q0 + 8 * KSTR;
        #pragma unroll
        for (int ks = 0; ks < 8; ks++) {
            const int kk = ks << 3;
            qf[ks][0] = f2tf32(q0[kk + tig] * 0.125f);
            qf[ks][1] = f2tf32(q8[kk + tig] * 0.125f);
            qf[ks][2] = f2tf32(q0[kk + tig + 4] * 0.125f);
            qf[ks][3] = f2tf32(q8[kk + tig + 4] * 0.125f);
        }
    }
    __syncthreads();  // Q staging consumed before prefetch overwrites buffer 0

    float oacc[8][4];
    #pragma unroll
    for (int ni = 0; ni < 8; ni++)
        #pragma unroll
        for (int r = 0; r < 4; r++) oacc[ni][r] = 0.0f;
    float mrow[2] = { -INFINITY, -INFINITY };
    float lrow[2] = { 0.0f, 0.0f };

    const int ntile = (Teff + 63) >> 6;

    // ---- KV gather into stage buffer via cp.async ----
    auto gather = [&](int kt) {
        const int t0 = kt << 6;
        const uint32_t kbase = smem_base + (uint32_t)((kt & 1) * KV_WORDS) * 4u;
        const uint32_t vbase = kbase + 64 * KSTR * 4u;
        for (int i = tid; i < 1024; i += 128) {
            int kj = i >> 4;
            int dc = (i & 15) << 2;
            int t = t0 + kj;
            const float* srcK = kg;
            const float* srcV = vg;
            int sz = 0;
            if (t < L) {
                const float* bp = memkv + (((size_t)t * BATCH + b) * NHEAD + h) * (2 * HCDIM);
                srcK = bp + dc;
                srcV = bp + HCDIM + dc;
                sz = 16;
            } else if (t < Teff) {
                int j = t - L;
                srcK = kg + ((size_t)j * BATCH + b) * CDIM + h * HCDIM + dc;
                srcV = vg + ((size_t)j * BATCH + b) * CDIM + h * HCDIM + dc;
                sz = 16;
            }
            cp16(kbase + (uint32_t)(kj * KSTR + dc) * 4u, srcK, sz);
            cp16(vbase + (uint32_t)(kj * VSTR + dc) * 4u, srcV, sz);
        }
        cp_commit();
    };

    if (ntile > 0) gather(0);

    for (int kt = 0; kt < ntile; kt++) {
        const int t0 = kt << 6;
        if (kt + 1 < ntile) { gather(kt + 1); cp_wait1(); }
        else                { cp_wait0(); }
        __syncthreads();

        const uint32_t* Kb = smu + (kt & 1) * KV_WORDS;
        const uint32_t* Vb = Kb + 64 * KSTR;

        // S = Q K^T (raw fp32 bits as tf32: truncation)
        float sv[8][4];
        #pragma unroll
        for (int ni = 0; ni < 8; ni++)
            #pragma unroll
            for (int r = 0; r < 4; r++) sv[ni][r] = 0.0f;

        #pragma unroll
        for (int ks = 0; ks < 8; ks++) {
            const int kk = ks << 3;
            #pragma unroll
            for (int ni = 0; ni < 8; ni++) {
                const uint32_t* bp = Kb + ((ni << 3) + g) * KSTR + kk + tig;
                mma_tf32(sv[ni], qf[ks][0], qf[ks][1], qf[ks][2], qf[ks][3],
                         bp[0], bp[4]);
            }
        }

        // Masking
        #pragma unroll
        for (int ni = 0; ni < 8; ni++) {
            #pragma unroll
            for (int cc = 0; cc < 2; cc++) {
                int t = t0 + (ni << 3) + (tig << 1) + cc;
                if (t >= Teff) {
                    sv[ni][cc] = -INFINITY;
                    sv[ni][2 + cc] = -INFINITY;
                } else if (t >= L) {
                    int jn = t - L;
                    int r0 = s0 + qrow0;
                    if (mask[((size_t)r0 * QS + jn) * BATCH + b]) sv[ni][cc] = -INFINITY;
                    if (mask[((size_t)(r0 + 8) * QS + jn) * BATCH + b]) sv[ni][2 + cc] = -INFINITY;
                }
            }
        }

        // Online softmax per row-half (row spread over 4 tig lanes)
        #pragma unroll
        for (int half = 0; half < 2; half++) {
            const int o0i = half << 1;
            float rm = -INFINITY;
            #pragma unroll
            for (int ni = 0; ni < 8; ni++)
                rm = fmaxf(rm, fmaxf(sv[ni][o0i], sv[ni][o0i + 1]));
            rm = fmaxf(rm, __shfl_xor_sync(0xffffffffu, rm, 1));
            rm = fmaxf(rm, __shfl_xor_sync(0xffffffffu, rm, 2));
            float mn = fmaxf(mrow[half], rm);
            float factor = (mn == -INFINITY) ? 1.0f : __expf(mrow[half] - mn);
            float rs = 0.0f;
            #pragma unroll
            for (int ni = 0; ni < 8; ni++) {
                #pragma unroll
                for (int cc = 0; cc < 2; cc++) {
                    float p = (mn == -INFINITY) ? 0.0f : __expf(sv[ni][o0i + cc] - mn);
                    sv[ni][o0i + cc] = p;
                    rs += p;
                }
            }
            rs += __shfl_xor_sync(0xffffffffu, rs, 1);
            rs += __shfl_xor_sync(0xffffffffu, rs, 2);
            lrow[half] = lrow[half] * factor + rs;
            mrow[half] = mn;
            #pragma unroll
            for (int ni = 0; ni < 8; ni++) {
                oacc[ni][o0i] *= factor;
                oacc[ni][o0i + 1] *= factor;
            }
        }

        // O += P V. P C-frag -> A-frag via intra-group shuffles:
        // col c of block ks lives at lane (g*4 + (c>>1)), slot (c&1).
        const int srcA = (lane & ~3) + (tig >> 1);
        const int srcB = srcA + 2;
        const int sel  = tig & 1;
        #pragma unroll
        for (int ks = 0; ks < 8; ks++) {
            float s0a = __shfl_sync(0xffffffffu, sv[ks][0], srcA);
            float s1a = __shfl_sync(0xffffffffu, sv[ks][1], srcA);
            float s2a = __shfl_sync(0xffffffffu, sv[ks][2], srcA);
            float s3a = __shfl_sync(0xffffffffu, sv[ks][3], srcA);
            float s0b = __shfl_sync(0xffffffffu, sv[ks][0], srcB);
            float s1b = __shfl_sync(0xffffffffu, sv[ks][1], srcB);
            float s2b = __shfl_sync(0xffffffffu, sv[ks][2], srcB);
            float s3b = __shfl_sync(0xffffffffu, sv[ks][3], srcB);
            uint32_t pa0 = f2tf32(sel ? s1a : s0a);   // P[g][8ks+tig]
            uint32_t pa1 = f2tf32(sel ? s3a : s2a);   // P[g+8][8ks+tig]
            uint32_t pa2 = f2tf32(sel ? s1b : s0b);   // P[g][8ks+tig+4]
            uint32_t pa3 = f2tf32(sel ? s3b : s2b);   // P[g+8][8ks+tig+4]

            const int kk = ks << 3;
            #pragma unroll
            for (int ni = 0; ni < 8; ni++) {
                const uint32_t* bp = Vb + (kk + tig) * VSTR + (ni << 3) + g;
                mma_tf32(oacc[ni], pa0, pa1, pa2, pa3, bp[0], bp[4 * VSTR]);
            }
        }
        __syncthreads();  // done reading this stage before it becomes prefetch target
    }

    // Normalize and write x[s][b][c] (all-masked rows -> 0)
    #pragma unroll
    for (int half = 0; half < 2; half++) {
        float inv = (lrow[half] > 0.0f) ? 1.0f / lrow[half] : 0.0f;
        int row = s0 + qrow0 + (half << 3);
        float* orow = xout + ((size_t)row * BATCH + b) * CDIM + h * HCDIM;
        #pragma unroll
        for (int ni = 0; ni < 8; ni++) {
            int col = (ni << 3) + (tig << 1);
            float2 v = make_float2(oacc[ni][(half << 1)] * inv,
                                   oacc[ni][(half << 1) + 1] * inv);
            *(float2*)(orow + col) = v;
        }
    }
}

// ---------------------------------------------------------------------------
// Launch
// ---------------------------------------------------------------------------
extern "C" void kernel_launch(void* const* d_in, const int* in_sizes, int n_in,
                              void* d_out, int out_size)
{
    const float*         xq     = (const float*)d_in[0];
    const int*           pad    = (const int*)d_in[1];
    const unsigned char* mask   = (const unsigned char*)d_in[2];
    const int*           memlen = (const int*)d_in[3];
    const float*         memkv  = (const float*)d_in[4];
    const float* Wq = (const float*)d_in[5];  const float* bq = (const float*)d_in[6];
    const float* Wk = (const float*)d_in[7];  const float* bk = (const float*)d_in[8];
    const float* Wv = (const float*)d_in[9];  const float* bv = (const float*)d_in[10];
    const float* Wo = (const float*)d_in[11]; const float* bo = (const float*)d_in[12];
    float* out = (float*)d_out;

    float *gq, *gk, *gv, *gx;
    cudaGetSymbolAddress((void**)&gq, g_q);
    cudaGetSymbolAddress((void**)&gk, g_k);
    cudaGetSymbolAddress((void**)&gv, g_v);
    cudaGetSymbolAddress((void**)&gx, g_x);

    dim3 gg(CDIM / 128, NTOK / 128);  // (8, 32)
    gemm_tf32_nt_bias<<<gg, 256>>>(xq, Wq, bq, gq);
    gemm_tf32_nt_bias<<<gg, 256>>>(xq, Wk, bk, gk);
    gemm_tf32_nt_bias<<<gg, 256>>>(xq, Wv, bv, gv);

    const int smem_bytes = 2 * KV_WORDS * (int)sizeof(uint32_t);  // 71680
    cudaFuncSetAttribute(attn_tc_kernel, cudaFuncAttributeMaxDynamicSharedMemorySize, smem_bytes);
    attn_tc_kernel<<<dim3(QS / 64, BATCH * NHEAD), 128, smem_bytes>>>(
        gq, gk, gv, memkv, memlen, pad, mask, gx);

    gemm_tf32_nt_bias<<<gg, 256>>>(gx, Wo, bo, out);
}